// round 8
// baseline (speedup 1.0000x reference)
#include <cuda_runtime.h>
#include <cuda_bf16.h>

// Radius-neighbor mean pooling, TWO kernels, parity double-buffered counters.
// Gather v3: supercell tiling. 125 CTAs, one per 4x4x4-cell tile; the 6^3-cell
// halo (~443 points) is staged in SMEM once (prefix-sum compaction), then the
// tile's ~65 outputs are processed warp-per-output / lane-per-stencil-cell
// entirely out of SMEM. Outputs are tile-binned by the bin kernel.

#define RADIUS   0.05f
#define R2       (RADIUS * RADIUS)
#define GRID     20
#define NCELLS   (GRID * GRID * GRID)   // 8000
#define CAP      16                     // pts/cell cap; lambda ~2.05, P(>=16)~6e-10
#define BCH      8

#define TILE     4                      // cells per tile edge
#define TDIM     (GRID / TILE)          // 5 tiles per axis
#define NTILES   (TDIM * TDIM * TDIM)   // 125
#define HALO     (TILE + 2)             // 6
#define HCELLS   (HALO * HALO * HALO)   // 216
#define SMAX     576                    // halo point capacity (E~443, 6 sigma)
#define CAP_OUT  192                    // outputs per tile cap (E~65.5)

#define GTHR     512                    // gather CTA size (16 warps)

__device__ int    g_counts2[2][NCELLS];
__device__ int    g_ocnt2[2][NTILES];
__device__ int    g_obin[NTILES * CAP_OUT];
__device__ float4 g_pos[NCELLS * CAP];      // x,y,z,pad
__device__ float4 g_ch [NCELLS * CAP * 2];  // c0..c3 | c4..c7
__device__ int    g_parity;
__device__ int    g_snap;

__device__ __forceinline__ int cell_coord(float p) {
    int c = (int)(p * (float)GRID);
    if (c < 0) c = 0;
    if (c > GRID - 1) c = GRID - 1;
    return c;
}

// ---------------------------------------------------------------------------
// Kernel 1: bin input points (pos + channels) AND bin output indices by tile.
// ---------------------------------------------------------------------------
__global__ void __launch_bounds__(128)
bin_points_kernel(const float* __restrict__ x,
                  const float* __restrict__ ipos,
                  const float* __restrict__ opos,
                  int n_in, int n_out) {
    int i = blockIdx.x * blockDim.x + threadIdx.x;

    int p = g_parity;                      // stable during this kernel
    if (i == 0) g_snap = p;

    if (i < n_out) {                       // bin this output into its tile
        float ox = opos[i * 3 + 0];
        float oy = opos[i * 3 + 1];
        float oz = opos[i * 3 + 2];
        int tile = ((cell_coord(ox) / TILE) * TDIM + (cell_coord(oy) / TILE)) * TDIM
                 + (cell_coord(oz) / TILE);
        int slot = atomicAdd(&g_ocnt2[p][tile], 1);
        if (slot < CAP_OUT) g_obin[tile * CAP_OUT + slot] = i;
    }

    if (i >= n_in) return;

    float px = ipos[i * 3 + 0];
    float py = ipos[i * 3 + 1];
    float pz = ipos[i * 3 + 2];
    int cell = (cell_coord(px) * GRID + cell_coord(py)) * GRID + cell_coord(pz);

    int slot = atomicAdd(&g_counts2[p][cell], 1);
    if (slot >= CAP) return;               // statistically unreachable

    int rec = cell * CAP + slot;
    g_pos[rec] = make_float4(px, py, pz, 0.0f);
    g_ch[rec * 2 + 0] = make_float4(x[0 * n_in + i], x[1 * n_in + i],
                                    x[2 * n_in + i], x[3 * n_in + i]);
    g_ch[rec * 2 + 1] = make_float4(x[4 * n_in + i], x[5 * n_in + i],
                                    x[6 * n_in + i], x[7 * n_in + i]);
}

// ---------------------------------------------------------------------------
// Kernel 2: one CTA per tile. Stage halo in SMEM, process tile outputs.
// Side jobs: zero other-parity counters, flip parity.
// ---------------------------------------------------------------------------
__global__ void __launch_bounds__(GTHR, 1)
gather_kernel(const float* __restrict__ opos,
              float* __restrict__ out,
              int n_out) {
    __shared__ float4 s_pos[SMAX];
    __shared__ float4 s_cha[SMAX];
    __shared__ float4 s_chb[SMAX];
    __shared__ int    s_cnt[HCELLS];
    __shared__ int    s_start[HCELLS];
    __shared__ int    s_wsum[8];

    int tid  = threadIdx.x;
    int gtid = blockIdx.x * GTHR + tid;

    int p = g_snap;                        // stable during this kernel

    // side jobs (125*512 = 64000 threads covers both arrays)
    if (gtid < NCELLS) g_counts2[1 - p][gtid] = 0;
    if (gtid < NTILES) g_ocnt2[1 - p][gtid] = 0;
    if (gtid == 0)     g_parity = 1 - p;

    int tile = blockIdx.x;
    int tx = tile / (TDIM * TDIM);
    int ty = (tile / TDIM) % TDIM;
    int tz = tile % TDIM;
    int bx0 = tx * TILE - 1;               // halo origin (may be -1)
    int by0 = ty * TILE - 1;
    int bz0 = tz * TILE - 1;

    // ---- stage 1: halo cell counts ----
    if (tid < HCELLS) {
        int hx = tid / (HALO * HALO);
        int hy = (tid / HALO) % HALO;
        int hz = tid % HALO;
        int cx = bx0 + hx, cy = by0 + hy, cz = bz0 + hz;
        int c = 0;
        if (cx >= 0 && cx < GRID && cy >= 0 && cy < GRID && cz >= 0 && cz < GRID) {
            c = __ldg(&g_counts2[p][(cx * GRID + cy) * GRID + cz]);
            if (c > CAP) c = CAP;
        }
        s_cnt[tid] = c;
    }
    __syncthreads();

    // ---- stage 2: block exclusive prefix sum over 216 counts ----
    if (tid < 256) {                       // 8 full warps
        int lane = tid & 31;
        int v = (tid < HCELLS) ? s_cnt[tid] : 0;
        int inc = v;
#pragma unroll
        for (int off = 1; off < 32; off <<= 1) {
            int n = __shfl_up_sync(0xFFFFFFFFu, inc, off);
            if (lane >= off) inc += n;
        }
        if (tid < HCELLS) s_start[tid] = inc - v;   // warp-local exclusive
        if (lane == 31) s_wsum[tid >> 5] = inc;
    }
    __syncthreads();
    if (tid < 8) {
        int v = s_wsum[tid];
        int inc = v;
#pragma unroll
        for (int off = 1; off < 8; off <<= 1) {
            int n = __shfl_up_sync(0x000000FFu, inc, off, 8);
            if (tid >= off) inc += n;
        }
        s_wsum[tid] = inc - v;                      // exclusive warp offset
    }
    __syncthreads();
    if (tid < HCELLS) {
        int st = s_start[tid] + s_wsum[tid >> 5];
        s_start[tid] = st;
        // deterministic clamp against SMAX overflow (statistically unreachable)
        int c = s_cnt[tid];
        int room = SMAX - st;
        if (room < 0) room = 0;
        if (c > room) c = room;
        s_cnt[tid] = c;
    }
    __syncthreads();

    // ---- stage 3: copy halo points into SMEM ----
    if (tid < HCELLS) {
        int c = s_cnt[tid];
        if (c > 0) {
            int hx = tid / (HALO * HALO);
            int hy = (tid / HALO) % HALO;
            int hz = tid % HALO;
            int cell = ((bx0 + hx) * GRID + (by0 + hy)) * GRID + (bz0 + hz);
            int base = cell * CAP;
            int st = s_start[tid];
            for (int k = 0; k < c; k++) {
                int rec = base + k;
                s_pos[st + k] = __ldg(&g_pos[rec]);
                s_cha[st + k] = __ldg(&g_ch[rec * 2 + 0]);
                s_chb[st + k] = __ldg(&g_ch[rec * 2 + 1]);
            }
        }
    }
    __syncthreads();

    // ---- stage 4: process this tile's outputs, warp per output ----
    int nout_t = g_ocnt2[p][tile];
    if (nout_t > CAP_OUT) nout_t = CAP_OUT;

    int wid  = tid >> 5;
    int lane = tid & 31;

    for (int j = wid; j < nout_t; j += GTHR / 32) {
        int o = g_obin[tile * CAP_OUT + j];
        float ox = __ldg(&opos[o * 3 + 0]);
        float oy = __ldg(&opos[o * 3 + 1]);
        float oz = __ldg(&opos[o * 3 + 2]);

        float cnt = 0.0f;
        float4 sa = make_float4(0.f, 0.f, 0.f, 0.f);
        float4 sb = make_float4(0.f, 0.f, 0.f, 0.f);

        if (lane < 27) {
            // local halo coords: base cell is inside the tile, so lx,ly,lz in [0,5]
            int lx = cell_coord(ox) - tx * TILE + (lane / 9);
            int ly = cell_coord(oy) - ty * TILE + ((lane / 3) % 3);
            int lz = cell_coord(oz) - tz * TILE + (lane % 3);
            int h  = (lx * HALO + ly) * HALO + lz;
            int c  = s_cnt[h];
            int st = s_start[h];
            for (int k = 0; k < c; k++) {
                float4 q = s_pos[st + k];
                float dx = ox - q.x;
                float dy = oy - q.y;
                float dz = oz - q.z;
                float d2 = fmaf(dx, dx, fmaf(dy, dy, dz * dz));
                if (d2 <= R2) {
                    cnt += 1.0f;
                    float4 a = s_cha[st + k];
                    float4 b = s_chb[st + k];
                    sa.x += a.x; sa.y += a.y; sa.z += a.z; sa.w += a.w;
                    sb.x += b.x; sb.y += b.y; sb.z += b.z; sb.w += b.w;
                }
            }
        }

        // warp butterfly reduction of {cnt, sa, sb}
#pragma unroll
        for (int off = 16; off > 0; off >>= 1) {
            cnt  += __shfl_xor_sync(0xFFFFFFFFu, cnt,  off);
            sa.x += __shfl_xor_sync(0xFFFFFFFFu, sa.x, off);
            sa.y += __shfl_xor_sync(0xFFFFFFFFu, sa.y, off);
            sa.z += __shfl_xor_sync(0xFFFFFFFFu, sa.z, off);
            sa.w += __shfl_xor_sync(0xFFFFFFFFu, sa.w, off);
            sb.x += __shfl_xor_sync(0xFFFFFFFFu, sb.x, off);
            sb.y += __shfl_xor_sync(0xFFFFFFFFu, sb.y, off);
            sb.z += __shfl_xor_sync(0xFFFFFFFFu, sb.z, off);
            sb.w += __shfl_xor_sync(0xFFFFFFFFu, sb.w, off);
        }

        if (lane < BCH) {
            float dem = cnt > 0.0f ? cnt : 1.0f;
            float inv = 1.0f / dem;
            float v = sa.x;
            if (lane == 1) v = sa.y;
            if (lane == 2) v = sa.z;
            if (lane == 3) v = sa.w;
            if (lane == 4) v = sb.x;
            if (lane == 5) v = sb.y;
            if (lane == 6) v = sb.z;
            if (lane == 7) v = sb.w;
            out[lane * n_out + o] = v * inv;
        }
    }
}

// ---------------------------------------------------------------------------
extern "C" void kernel_launch(void* const* d_in, const int* in_sizes, int n_in_arr,
                              void* d_out, int out_size) {
    const float* x    = (const float*)d_in[0];   // [B, n_in]
    const float* ipos = (const float*)d_in[1];   // [n_in, 3]
    const float* opos = (const float*)d_in[2];   // [n_out, 3]
    float* out = (float*)d_out;                  // [B, n_out]

    int n_in  = in_sizes[1] / 3;
    int n_out = in_sizes[2] / 3;

    bin_points_kernel<<<(n_in + 127) / 128, 128>>>(x, ipos, opos, n_in, n_out);

    gather_kernel<<<NTILES, GTHR>>>(opos, out, n_out);
}

// round 11
// speedup vs baseline: 1.6441x; 1.6441x over previous
#include <cuda_runtime.h>
#include <cuda_bf16.h>

// Radius-neighbor mean pooling, TWO kernels, parity double-buffered counters.
// Gather: one warp per output, one stencil cell per lane, 8-slot predicated
// fast path, slot-major layout. R11: FOLD warp reduction (correct; the R10
// transposed scheme summed the diagonal). Fold: pairs split channel halves
// and exchange the half they drop -> 9 shfl total for 8 channels; lane 4b
// ends with channel b's full total.

#define RADIUS   0.05f
#define R2       (RADIUS * RADIUS)
#define GRID     20
#define NCELLS   (GRID * GRID * GRID)   // 8000
#define CAP      16                     // pts/cell cap; lambda ~2.05, P(>=16)~6e-10
#define FAST     8                      // slots in the predicated fast path
#define BCH      8

__device__ int    g_counts2[2][NCELLS];
__device__ float4 g_pos[CAP * NCELLS];      // SLOT-MAJOR: [slot][cell]
__device__ float4 g_ch [CAP * NCELLS * 2];  // [slot][cell][2]: c0..c3 | c4..c7
__device__ int    g_parity;
__device__ int    g_snap;

__device__ __forceinline__ int cell_coord(float p) {
    int c = (int)(p * (float)GRID);
    if (c < 0) c = 0;
    if (c > GRID - 1) c = GRID - 1;
    return c;
}

// ---------------------------------------------------------------------------
// Kernel 1: bin all input points (slot-major records).
// ---------------------------------------------------------------------------
__global__ void __launch_bounds__(128)
bin_points_kernel(const float* __restrict__ x,
                  const float* __restrict__ ipos,
                  int n_in) {
    int i = blockIdx.x * blockDim.x + threadIdx.x;

    int p = g_parity;                      // stable during this kernel
    if (i == 0) g_snap = p;

    if (i >= n_in) return;

    float px = ipos[i * 3 + 0];
    float py = ipos[i * 3 + 1];
    float pz = ipos[i * 3 + 2];
    int cell = (cell_coord(px) * GRID + cell_coord(py)) * GRID + cell_coord(pz);

    int slot = atomicAdd(&g_counts2[p][cell], 1);
    if (slot >= CAP) return;               // statistically unreachable

    int rec = slot * NCELLS + cell;        // slot-major
    g_pos[rec] = make_float4(px, py, pz, 0.0f);
    g_ch[rec * 2 + 0] = make_float4(x[0 * n_in + i], x[1 * n_in + i],
                                    x[2 * n_in + i], x[3 * n_in + i]);
    g_ch[rec * 2 + 1] = make_float4(x[4 * n_in + i], x[5 * n_in + i],
                                    x[6 * n_in + i], x[7 * n_in + i]);
}

// ---------------------------------------------------------------------------
// Kernel 2: one WARP per output; lane l (< 27) owns one stencil cell.
// Side jobs: zero other-parity counters; flip parity.
// ---------------------------------------------------------------------------
__global__ void __launch_bounds__(128)
gather_kernel(const float* __restrict__ opos,
              float* __restrict__ out,
              int n_out) {
    int gtid = blockIdx.x * blockDim.x + threadIdx.x;
    int warp = gtid >> 5;
    int lane = threadIdx.x & 31;

    int p = g_snap;                        // stable during this kernel

    if (gtid < NCELLS) g_counts2[1 - p][gtid] = 0;   // prep next run
    if (gtid == 0) g_parity = 1 - p;                 // consumed next launch

    if (warp >= n_out) return;

    float ox = __ldg(&opos[warp * 3 + 0]);
    float oy = __ldg(&opos[warp * 3 + 1]);
    float oz = __ldg(&opos[warp * 3 + 2]);

    // epoch 0: per-lane cell + count (lane%3 fastest -> z-adjacent lanes)
    int c = 0;
    int cell = 0;
    if (lane < 27) {
        int cx = cell_coord(ox) + (lane / 9) - 1;
        int cy = cell_coord(oy) + ((lane / 3) % 3) - 1;
        int cz = cell_coord(oz) + (lane % 3) - 1;
        if (cx >= 0 && cx < GRID && cy >= 0 && cy < GRID &&
            cz >= 0 && cz < GRID) {
            cell = (cx * GRID + cy) * GRID + cz;
            c = __ldg(&g_counts2[p][cell]);
            if (c > CAP) c = CAP;
        }
    }

    float cnt = 0.0f;
    float s[BCH];
#pragma unroll
    for (int b = 0; b < BCH; b++) s[b] = 0.0f;

    // epoch 1: FAST predicated pos loads, all issued back-to-back
    float4 pt[FAST];
#pragma unroll
    for (int t = 0; t < FAST; t++)
        pt[t] = (t < c) ? __ldg(&g_pos[t * NCELLS + cell])
                        : make_float4(1e9f, 1e9f, 1e9f, 0.f);

#pragma unroll
    for (int t = 0; t < FAST; t++) {
        float dx = ox - pt[t].x;
        float dy = oy - pt[t].y;
        float dz = oz - pt[t].z;
        float d2 = fmaf(dx, dx, fmaf(dy, dy, dz * dz));
        if (d2 <= R2) {
            cnt += 1.0f;
            float4 a = __ldg(&g_ch[(t * NCELLS + cell) * 2 + 0]);
            float4 b = __ldg(&g_ch[(t * NCELLS + cell) * 2 + 1]);
            s[0] += a.x; s[1] += a.y; s[2] += a.z; s[3] += a.w;
            s[4] += b.x; s[5] += b.y; s[6] += b.z; s[7] += b.w;
        }
    }

    // rare tail: cells with more than FAST points (~0.8% of warps)
    for (int t = FAST; t < c; t++) {
        float4 q = __ldg(&g_pos[t * NCELLS + cell]);
        float dx = ox - q.x;
        float dy = oy - q.y;
        float dz = oz - q.z;
        float d2 = fmaf(dx, dx, fmaf(dy, dy, dz * dz));
        if (d2 <= R2) {
            cnt += 1.0f;
            float4 a = __ldg(&g_ch[(t * NCELLS + cell) * 2 + 0]);
            float4 b = __ldg(&g_ch[(t * NCELLS + cell) * 2 + 1]);
            s[0] += a.x; s[1] += a.y; s[2] += a.z; s[3] += a.w;
            s[4] += b.x; s[5] += b.y; s[6] += b.z; s[7] += b.w;
        }
    }

    // ---- fold warp reduction (8 channels, 9 shfl) ----
    // Step off=16 (bit4): keep 4 channels, send the 4 the partner keeps.
    //   After: t4[j] = channel (4*bit4 + j) summed over {l, l^16}.
    int b4 = (lane >> 4) & 1;
    int b3 = (lane >> 3) & 1;
    int b2 = (lane >> 2) & 1;

    float t4[4];
#pragma unroll
    for (int j = 0; j < 4; j++) {
        float keep = b4 ? s[j + 4] : s[j];
        float send = b4 ? s[j]     : s[j + 4];
        t4[j] = keep + __shfl_xor_sync(0xFFFFFFFFu, send, 16);
    }
    // Step off=8 (bit3): t2[j] = channel (4*b4 + 2*b3 + j) over 4 lanes.
    float t2[2];
#pragma unroll
    for (int j = 0; j < 2; j++) {
        float keep = b3 ? t4[j + 2] : t4[j];
        float send = b3 ? t4[j]     : t4[j + 2];
        t2[j] = keep + __shfl_xor_sync(0xFFFFFFFFu, send, 8);
    }
    // Step off=4 (bit2): t1 = channel (4*b4 + 2*b3 + b2) over 8 lanes.
    float t1;
    {
        float keep = b2 ? t2[1] : t2[0];
        float send = b2 ? t2[0] : t2[1];
        t1 = keep + __shfl_xor_sync(0xFFFFFFFFu, send, 4);
    }
    // Lanes l, l^1, l^2, l^3 share bits[2:5) -> same channel: finish butterfly.
    t1 += __shfl_xor_sync(0xFFFFFFFFu, t1, 2);
    t1 += __shfl_xor_sync(0xFFFFFFFFu, t1, 1);
    // Now lane l holds the FULL total of channel (l >> 2).

    // cnt: plain scalar butterfly (all lanes get the total)
#pragma unroll
    for (int off = 16; off > 0; off >>= 1)
        cnt += __shfl_xor_sync(0xFFFFFFFFu, cnt, off);

    // epilogue: lane 4b stores channel b
    if ((lane & 3) == 0) {
        float dem = cnt > 0.0f ? cnt : 1.0f;
        out[(lane >> 2) * n_out + warp] = t1 * (1.0f / dem);
    }
}

// ---------------------------------------------------------------------------
extern "C" void kernel_launch(void* const* d_in, const int* in_sizes, int n_in_arr,
                              void* d_out, int out_size) {
    const float* x    = (const float*)d_in[0];   // [B, n_in]
    const float* ipos = (const float*)d_in[1];   // [n_in, 3]
    const float* opos = (const float*)d_in[2];   // [n_out, 3]
    float* out = (float*)d_out;                  // [B, n_out]

    int n_in  = in_sizes[1] / 3;
    int n_out = in_sizes[2] / 3;

    bin_points_kernel<<<(n_in + 127) / 128, 128>>>(x, ipos, n_in);

    long long total_threads = (long long)n_out * 32;   // warp per output
    int block = 128;
    int grid  = (int)((total_threads + block - 1) / block);
    gather_kernel<<<grid, block>>>(opos, out, n_out);
}